// round 10
// baseline (speedup 1.0000x reference)
#include <cuda_runtime.h>
#include <cuda_fp16.h>
#include <math.h>
#include <stdint.h>

// Problem constants
constexpr int BB = 2;
constexpr int TT = 2048;
constexpr int DD = 1024;
constexpr int HH = 16;
constexpr int DH = 64;
constexpr int MROWS = BB * TT;          // 4096
constexpr int QKV_N = 3 * DD;           // 3072

// ---------------------------------------------------------------------------
// Scratch (static device allocations)
// ---------------------------------------------------------------------------
__device__ __half g_x[MROWS * DD];             // x fp16
__device__ __half g_wq[QKV_N * DD];            // w_qkv^T [N,K] fp16
__device__ __half g_wo[DD * DD];               // w_out^T [N,K] fp16
// layout [(b*16+h)][T][64]
__device__ __half g_q[BB*HH*TT*DH];
__device__ __half g_k[BB*HH*TT*DH];
__device__ __half g_v[BB*HH*TT*DH];
// attention output, layout [b*T+t][h*64+dh]
__device__ __half g_attn[MROWS * DD];

// ---------------------------------------------------------------------------
// PTX helpers
// ---------------------------------------------------------------------------
__device__ __forceinline__ uint32_t smem_u32(const void* p) {
    return (uint32_t)__cvta_generic_to_shared((void*)p);
}
__device__ __forceinline__ void cp16(uint32_t dst, const void* src) {
    asm volatile("cp.async.cg.shared.global [%0], [%1], 16;" :: "r"(dst), "l"(src));
}
__device__ __forceinline__ void ldsm4(uint32_t* r, uint32_t addr) {
    asm volatile("ldmatrix.sync.aligned.m8n8.x4.shared.b16 {%0,%1,%2,%3}, [%4];"
                 : "=r"(r[0]), "=r"(r[1]), "=r"(r[2]), "=r"(r[3]) : "r"(addr));
}
__device__ __forceinline__ void ldsm4t(uint32_t* r, uint32_t addr) {
    asm volatile("ldmatrix.sync.aligned.m8n8.x4.trans.shared.b16 {%0,%1,%2,%3}, [%4];"
                 : "=r"(r[0]), "=r"(r[1]), "=r"(r[2]), "=r"(r[3]) : "r"(addr));
}
__device__ __forceinline__ void mma_f16(float* d, const uint32_t* a,
                                        uint32_t b0, uint32_t b1) {
    asm volatile(
        "mma.sync.aligned.m16n8k16.row.col.f32.f16.f16.f32 "
        "{%0,%1,%2,%3}, {%4,%5,%6,%7}, {%8,%9}, {%0,%1,%2,%3};"
        : "+f"(d[0]), "+f"(d[1]), "+f"(d[2]), "+f"(d[3])
        : "r"(a[0]), "r"(a[1]), "r"(a[2]), "r"(a[3]), "r"(b0), "r"(b1));
}

// FFMA-only exp2 (no MUFU). Input already in log2 domain.
__device__ __forceinline__ float fast_exp2(float x) {
    x = fmaxf(x, -120.f);
    float r = x + 12582912.f;                    // round to nearest int
    int   n = __float_as_int(r) - 0x4B400000;
    float f = x - (r - 12582912.f);              // f in [-0.5, 0.5]
    float p = 1.f + f * (0.693147180f + f * (0.240226507f + f * (0.0555041087f +
              f * (0.00961812911f + f * 0.00133335581f))));
    return __int_as_float(__float_as_int(p) + (n << 23));
}

__device__ __forceinline__ uint32_t h2pack(float x, float y) {
    __half2 h = __floats2half2_rn(x, y);
    return *(uint32_t*)&h;
}

// ---------------------------------------------------------------------------
// Conversions
// ---------------------------------------------------------------------------
__global__ __launch_bounds__(256) void cast_kernel(
    const float* __restrict__ in, __half* __restrict__ out, int n4)
{
    int i = blockIdx.x * blockDim.x + threadIdx.x;
    if (i >= n4) return;
    float4 v = ((const float4*)in)[i];
    uint2 o;
    o.x = h2pack(v.x, v.y);
    o.y = h2pack(v.z, v.w);
    ((uint2*)out)[i] = o;
}

// [K,N] fp32 -> [N,K] fp16
__global__ __launch_bounds__(256) void transpose_h_kernel(
    const float* __restrict__ in, __half* __restrict__ out, int K, int N)
{
    __shared__ float tile[32][33];
    int n0 = blockIdx.x * 32, k0 = blockIdx.y * 32;
    int tx = threadIdx.x & 31, ty = threadIdx.x >> 5;
#pragma unroll
    for (int j = 0; j < 32; j += 8)
        tile[ty + j][tx] = in[(size_t)(k0 + ty + j) * N + n0 + tx];
    __syncthreads();
#pragma unroll
    for (int j = 0; j < 32; j += 8)
        out[(size_t)(n0 + ty + j) * K + k0 + tx] = __float2half_rn(tile[tx][ty + j]);
}

// ---------------------------------------------------------------------------
// fp16 single-pass GEMM: C = A @ B^T + bias.
// 128x128 tile, BK=64, 256 threads (8 warps 4x2), 3-stage cp.async pipeline
// (prefetch distance 2 chunks), one __syncthreads per chunk.
// ---------------------------------------------------------------------------
constexpr int ROW_B = 144;
constexpr int TILE_SM = 128 * ROW_B;      // 18432
constexpr int STAGE_SM = 2 * TILE_SM;     // 36864
constexpr int GEMM_SMEM = 3 * STAGE_SM;   // 110592
constexpr int NCHUNK_G = DD / 64;         // 16

// Q scale folded with log2(e) so attention can use exp2 directly.
constexpr float QSCALE = 0.125f * 1.44269504088896f;

__global__ __launch_bounds__(256, 2) void gemm_mma_kernel(
    const __half* __restrict__ A, const __half* __restrict__ Bw,
    const float* __restrict__ bias, float* __restrict__ C, int N, int mode)
{
    extern __shared__ char sm[];
    const uint32_t smb = smem_u32(sm);
    const int tid = threadIdx.x;
    const int wid = tid >> 5, lane = tid & 31;
    const int wm = wid >> 1, wn = wid & 1;
    const int m0 = blockIdx.y * 128;
    const int n0 = blockIdx.x * 128;

    const char* Ap = (const char*)A  + (size_t)m0 * DD * 2;
    const char* Bp = (const char*)Bw + (size_t)n0 * DD * 2;

    auto load_stage = [&](int c, int s) {
        const int k0b = c * 128;              // 64 fp16 = 128B
        const uint32_t sb = smb + s * STAGE_SM;
#pragma unroll
        for (int i = 0; i < 4; ++i) {
            const int cid = i * 256 + tid;    // 0..1023
            const int r = cid >> 3, c8 = (cid & 7) * 16;
            const size_t g = (size_t)r * 2048 + k0b + c8;
            const uint32_t so = r * ROW_B + c8;
            cp16(sb + so,           Ap + g);
            cp16(sb + TILE_SM + so, Bp + g);
        }
        asm volatile("cp.async.commit_group;" ::: "memory");
    };

    float acc[2][8][4];
#pragma unroll
    for (int mt = 0; mt < 2; ++mt)
#pragma unroll
        for (int nt = 0; nt < 8; ++nt)
#pragma unroll
            for (int j = 0; j < 4; ++j) acc[mt][nt][j] = 0.f;

    const int a_row = wm * 32 + (lane & 15);
    const int a_kb  = (lane >> 4) * 16;
    const int b_row = wn * 64 + (lane & 7) + ((lane >> 4) << 3);
    const int b_kb  = ((lane >> 3) & 1) * 16;

    load_stage(0, 0);
    load_stage(1, 1);

    for (int c = 0; c < NCHUNK_G; ++c) {
        // wait until current stage's group is done. In-order completion:
        // with >=2 pending groups, "<=1 pending" implies stage c landed.
        // On the LAST chunk only one group may be pending (stage c itself),
        // so wait_group 1 would NOT cover it -> wait_group 0 there.
        if (c + 1 < NCHUNK_G) {
            asm volatile("cp.async.wait_group 1;" ::: "memory");
        } else {
            asm volatile("cp.async.wait_group 0;" ::: "memory");
        }
        __syncthreads();
        if (c + 2 < NCHUNK_G) load_stage(c + 2, (c + 2) % 3);

        const uint32_t sb = smb + (c % 3) * STAGE_SM;
#pragma unroll
        for (int k16 = 0; k16 < 4; ++k16) {
            const int kb = k16 * 32;
            uint32_t ah[2][4], bw[4][4];
#pragma unroll
            for (int mt = 0; mt < 2; ++mt)
                ldsm4(ah[mt], sb + (a_row + mt * 16) * ROW_B + kb + a_kb);
#pragma unroll
            for (int p = 0; p < 4; ++p)
                ldsm4(bw[p], sb + TILE_SM + (b_row + p * 16) * ROW_B + kb + b_kb);
#pragma unroll
            for (int mt = 0; mt < 2; ++mt)
#pragma unroll
                for (int nt = 0; nt < 8; ++nt) {
                    const int p = nt >> 1, h = (nt & 1) * 2;
                    mma_f16(acc[mt][nt], ah[mt], bw[p][h], bw[p][h + 1]);
                }
        }
    }

    if (mode == 0) {
#pragma unroll
        for (int mt = 0; mt < 2; ++mt) {
            const int r0 = m0 + wm * 32 + mt * 16 + (lane >> 2);
#pragma unroll
            for (int nt = 0; nt < 8; ++nt) {
                const int cc = n0 + wn * 64 + nt * 8 + (lane & 3) * 2;
                const float2 b2 = *(const float2*)(bias + cc);
                *(float2*)(C + (size_t)r0 * N + cc) =
                    make_float2(acc[mt][nt][0] + b2.x, acc[mt][nt][1] + b2.y);
                *(float2*)(C + (size_t)(r0 + 8) * N + cc) =
                    make_float2(acc[mt][nt][2] + b2.x, acc[mt][nt][3] + b2.y);
            }
        }
    } else {
        // QKV epilogue: q (xQSCALE, log2 domain) / k / v, fp16
        const int which = n0 >> 10;
        __half* dst = (which == 0) ? g_q : (which == 1) ? g_k : g_v;
        const float sc = (which == 0) ? QSCALE : 1.f;
#pragma unroll
        for (int mt = 0; mt < 2; ++mt) {
            const int r0 = m0 + wm * 32 + mt * 16 + (lane >> 2);
#pragma unroll
            for (int nt = 0; nt < 8; ++nt) {
                const int cc = n0 + wn * 64 + nt * 8 + (lane & 3) * 2;
                const int h = (cc & 1023) >> 6, dh = cc & 63;
                const float2 b2 = *(const float2*)(bias + cc);
#pragma unroll
                for (int half_i = 0; half_i < 2; ++half_i) {
                    const int r = r0 + half_i * 8;
                    const int bq = r >> 11, tq = r & 2047;
                    const size_t off = ((size_t)(bq * 16 + h) * 2048 + tq) * 64 + dh;
                    *(uint32_t*)(dst + off) =
                        h2pack((acc[mt][nt][2 * half_i] + b2.x) * sc,
                               (acc[mt][nt][2 * half_i + 1] + b2.y) * sc);
                }
            }
        }
    }
}

// ---------------------------------------------------------------------------
// Tensor-core flash attention, causal, fp16, exp2-domain softmax.
// CTA: 128 q rows, 8 warps (16 rows each), KV tiles of 64, 3-stage cp.async
// KV pipeline, one __syncthreads per tile.
// smem: Q [128][144B] + 3 stages x {K, V}[64][144B]  = 73728 B.
// ---------------------------------------------------------------------------
constexpr int AT_STG_OFF = 18432;
constexpr int AT_ARR     = 64 * ROW_B;        // 9216
constexpr int AT_STG     = 2 * AT_ARR;        // 18432
constexpr int AT_SMEM    = AT_STG_OFF + 3 * AT_STG;   // 73728

__global__ __launch_bounds__(256, 2) void flash_attn_tc_kernel()
{
    extern __shared__ char sm[];
    const uint32_t smb = smem_u32(sm);
    const int tid = threadIdx.x, wid = tid >> 5, lane = tid & 31;
    const int bx = (int)gridDim.x - 1 - (int)blockIdx.x;   // heavy blocks first
    const int i0 = bx * 128;
    const int ntile = 2 * bx + 2;
    const int bh = blockIdx.y;
    const size_t head2 = (size_t)bh * TT * DH * 2;

    const char* q_g = (const char*)g_q + head2 + (size_t)i0 * DH * 2;
    const char* k_g = (const char*)g_k + head2;
    const char* v_g = (const char*)g_v + head2;

#pragma unroll
    for (int it = 0; it < 4; ++it) {
        int cid = it * 256 + tid;
        int row = cid >> 3, c8 = (cid & 7) * 16;
        cp16(smb + row * ROW_B + c8, q_g + row * 128 + c8);
    }
    asm volatile("cp.async.commit_group;" ::: "memory");

    auto load_kv = [&](int t, int s) {
        const uint32_t sb = smb + AT_STG_OFF + s * AT_STG;
        const int j0b = t * 64 * 128;
#pragma unroll
        for (int it = 0; it < 2; ++it) {
            int cid = it * 256 + tid;
            int row = cid >> 3, c8 = (cid & 7) * 16;
            uint32_t so = row * ROW_B + c8;
            int go = j0b + row * 128 + c8;
            cp16(sb + so,          k_g + go);
            cp16(sb + AT_ARR + so, v_g + go);
        }
        asm volatile("cp.async.commit_group;" ::: "memory");
    };
    load_kv(0, 0);

    // Q fragments (Q group is older than kv0 -> done once <=1 pending)
    asm volatile("cp.async.wait_group 1;" ::: "memory");
    __syncthreads();
    uint32_t qf[4][4];
    {
        const uint32_t a_off = (wid * 16 + (lane & 15)) * ROW_B + (lane >> 4) * 16;
#pragma unroll
        for (int kc = 0; kc < 4; ++kc)
            ldsm4(qf[kc], smb + a_off + kc * 32);
    }
    load_kv(1, 1);

    float oacc[8][4];
#pragma unroll
    for (int nt = 0; nt < 8; ++nt)
#pragma unroll
        for (int j = 0; j < 4; ++j) oacc[nt][j] = 0.f;
    float mrow[2] = {-1e30f, -1e30f}, lrow[2] = {0.f, 0.f};

    const uint32_t kb_off = ((lane & 7) + ((lane >> 4) << 3)) * ROW_B +
                            ((lane >> 3) & 1) * 16;
    const uint32_t vrow = (lane & 7) + (((lane >> 3) & 1) << 3);
    const uint32_t vcol = (lane >> 4) * 16;

    for (int t = 0; t < ntile; ++t) {
        if (t + 1 < ntile) {
            asm volatile("cp.async.wait_group 1;" ::: "memory");
        } else {
            asm volatile("cp.async.wait_group 0;" ::: "memory");
        }
        __syncthreads();
        if (t + 2 < ntile) load_kv(t + 2, (t + 2) % 3);

        const uint32_t sb = smb + AT_STG_OFF + (t % 3) * AT_STG;
        const int j0 = t * 64;

        // S = Q @ K^T (scores already in log2 domain via QSCALE)
        float sacc[8][4];
#pragma unroll
        for (int nt = 0; nt < 8; ++nt)
#pragma unroll
            for (int j = 0; j < 4; ++j) sacc[nt][j] = 0.f;

#pragma unroll
        for (int kc = 0; kc < 4; ++kc) {
#pragma unroll
            for (int p = 0; p < 4; ++p) {
                uint32_t kh4[4];
                ldsm4(kh4, sb + kb_off + p * (16 * ROW_B) + kc * 32);
                mma_f16(sacc[2 * p],     qf[kc], kh4[0], kh4[1]);
                mma_f16(sacc[2 * p + 1], qf[kc], kh4[2], kh4[3]);
            }
        }

        // causal mask
        if (j0 + 63 > i0 + wid * 16) {
#pragma unroll
            for (int i = 0; i < 2; ++i) {
                const int qi = i0 + wid * 16 + (lane >> 2) + 8 * i;
#pragma unroll
                for (int nt = 0; nt < 8; ++nt) {
                    const int kt0 = j0 + nt * 8 + (lane & 3) * 2;
                    if (kt0 > qi)     sacc[nt][2 * i]     = -1e30f;
                    if (kt0 + 1 > qi) sacc[nt][2 * i + 1] = -1e30f;
                }
            }
        }

        // online softmax (exp2 domain)
#pragma unroll
        for (int i = 0; i < 2; ++i) {
            float mx = -1e30f;
#pragma unroll
            for (int nt = 0; nt < 8; ++nt)
                mx = fmaxf(mx, fmaxf(sacc[nt][2 * i], sacc[nt][2 * i + 1]));
            mx = fmaxf(mx, __shfl_xor_sync(0xffffffffu, mx, 1));
            mx = fmaxf(mx, __shfl_xor_sync(0xffffffffu, mx, 2));
            const float mn = fmaxf(mrow[i], mx);
            const float al = fast_exp2(mrow[i] - mn);
            mrow[i] = mn;
            float sum = 0.f;
#pragma unroll
            for (int nt = 0; nt < 8; ++nt) {
                float p0 = fast_exp2(sacc[nt][2 * i] - mn);
                float p1 = fast_exp2(sacc[nt][2 * i + 1] - mn);
                sacc[nt][2 * i] = p0;
                sacc[nt][2 * i + 1] = p1;
                sum += p0 + p1;
            }
            sum += __shfl_xor_sync(0xffffffffu, sum, 1);
            sum += __shfl_xor_sync(0xffffffffu, sum, 2);
            lrow[i] = lrow[i] * al + sum;
#pragma unroll
            for (int nt = 0; nt < 8; ++nt) {
                oacc[nt][2 * i] *= al;
                oacc[nt][2 * i + 1] *= al;
            }
        }

        // O += P @ V
#pragma unroll
        for (int kt = 0; kt < 4; ++kt) {
            uint32_t pa[4];
            pa[0] = h2pack(sacc[2 * kt][0],     sacc[2 * kt][1]);
            pa[1] = h2pack(sacc[2 * kt][2],     sacc[2 * kt][3]);
            pa[2] = h2pack(sacc[2 * kt + 1][0], sacc[2 * kt + 1][1]);
            pa[3] = h2pack(sacc[2 * kt + 1][2], sacc[2 * kt + 1][3]);
#pragma unroll
            for (int vd = 0; vd < 4; ++vd) {
                uint32_t vh4[4];
                ldsm4t(vh4, sb + AT_ARR + (kt * 16 + vrow) * ROW_B + vcol + vd * 32);
                mma_f16(oacc[2 * vd],     pa, vh4[0], vh4[1]);
                mma_f16(oacc[2 * vd + 1], pa, vh4[2], vh4[3]);
            }
        }
    }

    // epilogue: normalize, write fp16 [b*T+t][h*64+dh]
    const int b = bh >> 4, h = bh & 15;
#pragma unroll
    for (int i = 0; i < 2; ++i) {
        const float inv = 1.0f / lrow[i];
        const int trow = i0 + wid * 16 + (lane >> 2) + 8 * i;
        const size_t rbase = (size_t)(b * TT + trow) * DD + h * 64;
#pragma unroll
        for (int nt = 0; nt < 8; ++nt) {
            const int col = nt * 8 + (lane & 3) * 2;
            *(uint32_t*)(g_attn + rbase + col) =
                h2pack(oacc[nt][2 * i] * inv, oacc[nt][2 * i + 1] * inv);
        }
    }
}

// ---------------------------------------------------------------------------
extern "C" void kernel_launch(void* const* d_in, const int* in_sizes, int n_in,
                              void* d_out, int out_size)
{
    const float* x     = (const float*)d_in[0];
    const float* w_qkv = (const float*)d_in[1];
    const float* b_qkv = (const float*)d_in[2];
    const float* w_out = (const float*)d_in[3];
    const float* b_out = (const float*)d_in[4];
    float* out = (float*)d_out;

    cudaFuncSetAttribute(gemm_mma_kernel,
                         cudaFuncAttributeMaxDynamicSharedMemorySize, GEMM_SMEM);
    cudaFuncSetAttribute(flash_attn_tc_kernel,
                         cudaFuncAttributeMaxDynamicSharedMemorySize, AT_SMEM);

    __half *xh, *wq, *wo, *ah;
    cudaGetSymbolAddress((void**)&xh, g_x);
    cudaGetSymbolAddress((void**)&wq, g_wq);
    cudaGetSymbolAddress((void**)&wo, g_wo);
    cudaGetSymbolAddress((void**)&ah, g_attn);

    // 1. Cast x -> fp16
    cast_kernel<<<(MROWS * DD / 4 + 255) / 256, 256>>>(x, xh, MROWS * DD / 4);
    // 2. Transpose weights -> fp16 [N,K]
    transpose_h_kernel<<<dim3(QKV_N / 32, DD / 32), 256>>>(w_qkv, wq, DD, QKV_N);
    transpose_h_kernel<<<dim3(DD / 32, DD / 32), 256>>>(w_out, wo, DD, DD);
    // 3. QKV projection -> q/k/v fp16 (q pre-scaled into log2 domain)
    gemm_mma_kernel<<<dim3(QKV_N / 128, MROWS / 128), 256, GEMM_SMEM>>>(
        xh, wq, b_qkv, nullptr, QKV_N, 1);
    // 4. Flash attention -> attn fp16
    flash_attn_tc_kernel<<<dim3(TT / 128, BB * HH), 256, AT_SMEM>>>();
    // 5. Output projection (fp32 out)
    gemm_mma_kernel<<<dim3(DD / 128, MROWS / 128), 256, GEMM_SMEM>>>(
        ah, wo, b_out, out, DD, 0);
}

// round 11
// speedup vs baseline: 1.5462x; 1.5462x over previous
#include <cuda_runtime.h>
#include <cuda_fp16.h>
#include <math.h>
#include <stdint.h>

// Problem constants
constexpr int BB = 2;
constexpr int TT = 2048;
constexpr int DD = 1024;
constexpr int HH = 16;
constexpr int DH = 64;
constexpr int MROWS = BB * TT;          // 4096
constexpr int QKV_N = 3 * DD;           // 3072

// ---------------------------------------------------------------------------
// Scratch (static device allocations)
// ---------------------------------------------------------------------------
__device__ __half g_x[MROWS * DD];             // x fp16
__device__ __half g_wq[QKV_N * DD];            // w_qkv^T [N,K] fp16
__device__ __half g_wo[DD * DD];               // w_out^T [N,K] fp16
// layout [(b*16+h)][T][64]
__device__ __half g_q[BB*HH*TT*DH];
__device__ __half g_k[BB*HH*TT*DH];
__device__ __half g_v[BB*HH*TT*DH];
// attention output, layout [b*T+t][h*64+dh]
__device__ __half g_attn[MROWS * DD];

// ---------------------------------------------------------------------------
// PTX helpers
// ---------------------------------------------------------------------------
__device__ __forceinline__ uint32_t smem_u32(const void* p) {
    return (uint32_t)__cvta_generic_to_shared((void*)p);
}
__device__ __forceinline__ void cp16(uint32_t dst, const void* src) {
    asm volatile("cp.async.cg.shared.global [%0], [%1], 16;" :: "r"(dst), "l"(src));
}
__device__ __forceinline__ void ldsm4(uint32_t* r, uint32_t addr) {
    asm volatile("ldmatrix.sync.aligned.m8n8.x4.shared.b16 {%0,%1,%2,%3}, [%4];"
                 : "=r"(r[0]), "=r"(r[1]), "=r"(r[2]), "=r"(r[3]) : "r"(addr));
}
__device__ __forceinline__ void ldsm4t(uint32_t* r, uint32_t addr) {
    asm volatile("ldmatrix.sync.aligned.m8n8.x4.trans.shared.b16 {%0,%1,%2,%3}, [%4];"
                 : "=r"(r[0]), "=r"(r[1]), "=r"(r[2]), "=r"(r[3]) : "r"(addr));
}
__device__ __forceinline__ void mma_f16(float* d, const uint32_t* a,
                                        uint32_t b0, uint32_t b1) {
    asm volatile(
        "mma.sync.aligned.m16n8k16.row.col.f32.f16.f16.f32 "
        "{%0,%1,%2,%3}, {%4,%5,%6,%7}, {%8,%9}, {%0,%1,%2,%3};"
        : "+f"(d[0]), "+f"(d[1]), "+f"(d[2]), "+f"(d[3])
        : "r"(a[0]), "r"(a[1]), "r"(a[2]), "r"(a[3]), "r"(b0), "r"(b1));
}

// FFMA-only exp2 (no MUFU). Input already in log2 domain.
__device__ __forceinline__ float fast_exp2(float x) {
    x = fmaxf(x, -120.f);
    float r = x + 12582912.f;                    // round to nearest int
    int   n = __float_as_int(r) - 0x4B400000;
    float f = x - (r - 12582912.f);              // f in [-0.5, 0.5]
    float p = 1.f + f * (0.693147180f + f * (0.240226507f + f * (0.0555041087f +
              f * (0.00961812911f + f * 0.00133335581f))));
    return __int_as_float(__float_as_int(p) + (n << 23));
}

__device__ __forceinline__ uint32_t h2pack(float x, float y) {
    __half2 h = __floats2half2_rn(x, y);
    return *(uint32_t*)&h;
}

// ---------------------------------------------------------------------------
// Fused prep: cast x -> fp16  |  transpose w_qkv  |  transpose w_out
// One launch. Blocks [0, 4096) cast; [4096, 7168) wq; [7168, 8192) wo.
// ---------------------------------------------------------------------------
constexpr int PREP_CAST_BLKS = (MROWS * DD / 4) / 256;          // 4096
constexpr int PREP_WQ_BLKS   = (QKV_N / 32) * (DD / 32);        // 3072
constexpr int PREP_WO_BLKS   = (DD / 32) * (DD / 32);           // 1024
constexpr int PREP_BLKS      = PREP_CAST_BLKS + PREP_WQ_BLKS + PREP_WO_BLKS;

__global__ __launch_bounds__(256) void prep_kernel(
    const float* __restrict__ x,
    const float* __restrict__ w_qkv,
    const float* __restrict__ w_out)
{
    const int bid = blockIdx.x;
    if (bid < PREP_CAST_BLKS) {
        // cast x
        int i = bid * 256 + threadIdx.x;
        float4 v = ((const float4*)x)[i];
        uint2 o;
        o.x = h2pack(v.x, v.y);
        o.y = h2pack(v.z, v.w);
        ((uint2*)g_x)[i] = o;
        return;
    }
    // transpose path
    const float* in;
    __half* out;
    int K, N, tb;
    if (bid < PREP_CAST_BLKS + PREP_WQ_BLKS) {
        in = w_qkv; out = g_wq; K = DD; N = QKV_N;
        tb = bid - PREP_CAST_BLKS;
    } else {
        in = w_out; out = g_wo; K = DD; N = DD;
        tb = bid - PREP_CAST_BLKS - PREP_WQ_BLKS;
    }
    const int nblk = N / 32;
    const int n0 = (tb % nblk) * 32, k0 = (tb / nblk) * 32;
    __shared__ float tile[32][33];
    int tx = threadIdx.x & 31, ty = threadIdx.x >> 5;
#pragma unroll
    for (int j = 0; j < 32; j += 8)
        tile[ty + j][tx] = in[(size_t)(k0 + ty + j) * N + n0 + tx];
    __syncthreads();
#pragma unroll
    for (int j = 0; j < 32; j += 8)
        out[(size_t)(n0 + ty + j) * K + k0 + tx] = __float2half_rn(tile[tx][ty + j]);
}

// ---------------------------------------------------------------------------
// fp16 single-pass GEMM: C = A @ B^T + bias.  (round-9 structure, verified)
// 128x128 tile, BK=64, 256 threads (8 warps 4x2), 2-stage cp.async,
// ONE __syncthreads per K-chunk (wait -> sync -> issue next -> compute).
// ---------------------------------------------------------------------------
constexpr int ROW_B = 144;
constexpr int TILE_SM = 128 * ROW_B;      // 18432
constexpr int STAGE_SM = 2 * TILE_SM;     // 36864
constexpr int GEMM_SMEM = 2 * STAGE_SM;   // 73728
constexpr int NCHUNK_G = DD / 64;         // 16

// Q scale folded with log2(e) so attention can use exp2 directly.
constexpr float QSCALE = 0.125f * 1.44269504088896f;

__global__ __launch_bounds__(256, 2) void gemm_mma_kernel(
    const __half* __restrict__ A, const __half* __restrict__ Bw,
    const float* __restrict__ bias, float* __restrict__ C, int N, int mode)
{
    extern __shared__ char sm[];
    const uint32_t smb = smem_u32(sm);
    const int tid = threadIdx.x;
    const int wid = tid >> 5, lane = tid & 31;
    const int wm = wid >> 1, wn = wid & 1;
    const int m0 = blockIdx.y * 128;
    const int n0 = blockIdx.x * 128;

    const char* Ap = (const char*)A  + (size_t)m0 * DD * 2;
    const char* Bp = (const char*)Bw + (size_t)n0 * DD * 2;

    auto load_stage = [&](int c, int s) {
        const int k0b = c * 128;              // 64 fp16 = 128B
        const uint32_t sb = smb + s * STAGE_SM;
#pragma unroll
        for (int i = 0; i < 4; ++i) {
            const int cid = i * 256 + tid;    // 0..1023
            const int r = cid >> 3, c8 = (cid & 7) * 16;
            const size_t g = (size_t)r * 2048 + k0b + c8;
            const uint32_t so = r * ROW_B + c8;
            cp16(sb + so,           Ap + g);
            cp16(sb + TILE_SM + so, Bp + g);
        }
        asm volatile("cp.async.commit_group;" ::: "memory");
    };

    float acc[2][8][4];
#pragma unroll
    for (int mt = 0; mt < 2; ++mt)
#pragma unroll
        for (int nt = 0; nt < 8; ++nt)
#pragma unroll
            for (int j = 0; j < 4; ++j) acc[mt][nt][j] = 0.f;

    const int a_row = wm * 32 + (lane & 15);
    const int a_kb  = (lane >> 4) * 16;
    const int b_row = wn * 64 + (lane & 7) + ((lane >> 4) << 3);
    const int b_kb  = ((lane >> 3) & 1) * 16;

    load_stage(0, 0);

    for (int c = 0; c < NCHUNK_G; ++c) {
        asm volatile("cp.async.wait_group 0;" ::: "memory");
        __syncthreads();
        if (c + 1 < NCHUNK_G) load_stage(c + 1, (c + 1) & 1);

        const uint32_t sb = smb + (c & 1) * STAGE_SM;
#pragma unroll
        for (int k16 = 0; k16 < 4; ++k16) {
            const int kb = k16 * 32;
            uint32_t ah[2][4], bw[4][4];
#pragma unroll
            for (int mt = 0; mt < 2; ++mt)
                ldsm4(ah[mt], sb + (a_row + mt * 16) * ROW_B + kb + a_kb);
#pragma unroll
            for (int p = 0; p < 4; ++p)
                ldsm4(bw[p], sb + TILE_SM + (b_row + p * 16) * ROW_B + kb + b_kb);
#pragma unroll
            for (int mt = 0; mt < 2; ++mt)
#pragma unroll
                for (int nt = 0; nt < 8; ++nt) {
                    const int p = nt >> 1, h = (nt & 1) * 2;
                    mma_f16(acc[mt][nt], ah[mt], bw[p][h], bw[p][h + 1]);
                }
        }
    }

    if (mode == 0) {
#pragma unroll
        for (int mt = 0; mt < 2; ++mt) {
            const int r0 = m0 + wm * 32 + mt * 16 + (lane >> 2);
#pragma unroll
            for (int nt = 0; nt < 8; ++nt) {
                const int cc = n0 + wn * 64 + nt * 8 + (lane & 3) * 2;
                const float2 b2 = *(const float2*)(bias + cc);
                *(float2*)(C + (size_t)r0 * N + cc) =
                    make_float2(acc[mt][nt][0] + b2.x, acc[mt][nt][1] + b2.y);
                *(float2*)(C + (size_t)(r0 + 8) * N + cc) =
                    make_float2(acc[mt][nt][2] + b2.x, acc[mt][nt][3] + b2.y);
            }
        }
    } else {
        // QKV epilogue: q (xQSCALE, log2 domain) / k / v, fp16
        const int which = n0 >> 10;
        __half* dst = (which == 0) ? g_q : (which == 1) ? g_k : g_v;
        const float sc = (which == 0) ? QSCALE : 1.f;
#pragma unroll
        for (int mt = 0; mt < 2; ++mt) {
            const int r0 = m0 + wm * 32 + mt * 16 + (lane >> 2);
#pragma unroll
            for (int nt = 0; nt < 8; ++nt) {
                const int cc = n0 + wn * 64 + nt * 8 + (lane & 3) * 2;
                const int h = (cc & 1023) >> 6, dh = cc & 63;
                const float2 b2 = *(const float2*)(bias + cc);
#pragma unroll
                for (int half_i = 0; half_i < 2; ++half_i) {
                    const int r = r0 + half_i * 8;
                    const int bq = r >> 11, tq = r & 2047;
                    const size_t off = ((size_t)(bq * 16 + h) * 2048 + tq) * 64 + dh;
                    *(uint32_t*)(dst + off) =
                        h2pack((acc[mt][nt][2 * half_i] + b2.x) * sc,
                               (acc[mt][nt][2 * half_i + 1] + b2.y) * sc);
                }
            }
        }
    }
}

// ---------------------------------------------------------------------------
// Tensor-core flash attention, causal, fp16, exp2-domain softmax.
// Round-9 structure + warp-level skip of fully-masked tiles.
// CTA: 128 q rows, 8 warps (16 rows each), KV tiles of 64, 2-stage cp.async,
// ONE __syncthreads per KV tile.
// smem: Q [128][144B] + 2 stages x {K, V}[64][144B]  = 55296 B.
// ---------------------------------------------------------------------------
constexpr int AT_STG_OFF = 18432;
constexpr int AT_ARR     = 64 * ROW_B;        // 9216
constexpr int AT_STG     = 2 * AT_ARR;        // 18432
constexpr int AT_SMEM    = AT_STG_OFF + 2 * AT_STG;   // 55296

__global__ __launch_bounds__(256, 2) void flash_attn_tc_kernel()
{
    extern __shared__ char sm[];
    const uint32_t smb = smem_u32(sm);
    const int tid = threadIdx.x, wid = tid >> 5, lane = tid & 31;
    const int bx = (int)gridDim.x - 1 - (int)blockIdx.x;   // heavy blocks first
    const int i0 = bx * 128;
    const int ntile = 2 * bx + 2;
    const int bh = blockIdx.y;
    const size_t head2 = (size_t)bh * TT * DH * 2;

    const char* q_g = (const char*)g_q + head2 + (size_t)i0 * DH * 2;
    const char* k_g = (const char*)g_k + head2;
    const char* v_g = (const char*)g_v + head2;

#pragma unroll
    for (int it = 0; it < 4; ++it) {
        int cid = it * 256 + tid;
        int row = cid >> 3, c8 = (cid & 7) * 16;
        cp16(smb + row * ROW_B + c8, q_g + row * 128 + c8);
    }
    asm volatile("cp.async.commit_group;" ::: "memory");

    auto load_kv = [&](int t, int s) {
        const uint32_t sb = smb + AT_STG_OFF + s * AT_STG;
        const int j0b = t * 64 * 128;
#pragma unroll
        for (int it = 0; it < 2; ++it) {
            int cid = it * 256 + tid;
            int row = cid >> 3, c8 = (cid & 7) * 16;
            uint32_t so = row * ROW_B + c8;
            int go = j0b + row * 128 + c8;
            cp16(sb + so,          k_g + go);
            cp16(sb + AT_ARR + so, v_g + go);
        }
        asm volatile("cp.async.commit_group;" ::: "memory");
    };
    load_kv(0, 0);

    // Q fragments
    asm volatile("cp.async.wait_group 1;" ::: "memory");
    __syncthreads();
    uint32_t qf[4][4];
    {
        const uint32_t a_off = (wid * 16 + (lane & 15)) * ROW_B + (lane >> 4) * 16;
#pragma unroll
        for (int kc = 0; kc < 4; ++kc)
            ldsm4(qf[kc], smb + a_off + kc * 32);
    }

    float oacc[8][4];
#pragma unroll
    for (int nt = 0; nt < 8; ++nt)
#pragma unroll
        for (int j = 0; j < 4; ++j) oacc[nt][j] = 0.f;
    float mrow[2] = {-1e30f, -1e30f}, lrow[2] = {0.f, 0.f};

    const uint32_t kb_off = ((lane & 7) + ((lane >> 4) << 3)) * ROW_B +
                            ((lane >> 3) & 1) * 16;
    const uint32_t vrow = (lane & 7) + (((lane >> 3) & 1) << 3);
    const uint32_t vcol = (lane >> 4) * 16;
    const int rowmax = i0 + wid * 16 + 15;   // warp's last q row

    for (int t = 0; t < ntile; ++t) {
        asm volatile("cp.async.wait_group 0;" ::: "memory");
        __syncthreads();
        if (t + 1 < ntile) load_kv(t + 1, (t + 1) & 1);

        const uint32_t sb = smb + AT_STG_OFF + (t & 1) * AT_STG;
        const int j0 = t * 64;

        // Warp-uniform skip: all 16 of this warp's q rows < j0 -> tile is a
        // provable no-op (every score masked, P == 0, max < mrow since the
        // warp's first tile t=0 (j0=0) is never skipped and sets mrow/lrow).
        if (j0 > rowmax) continue;

        // S = Q @ K^T (scores already in log2 domain via QSCALE)
        float sacc[8][4];
#pragma unroll
        for (int nt = 0; nt < 8; ++nt)
#pragma unroll
            for (int j = 0; j < 4; ++j) sacc[nt][j] = 0.f;

#pragma unroll
        for (int kc = 0; kc < 4; ++kc) {
#pragma unroll
            for (int p = 0; p < 4; ++p) {
                uint32_t kh4[4];
                ldsm4(kh4, sb + kb_off + p * (16 * ROW_B) + kc * 32);
                mma_f16(sacc[2 * p],     qf[kc], kh4[0], kh4[1]);
                mma_f16(sacc[2 * p + 1], qf[kc], kh4[2], kh4[3]);
            }
        }

        // causal mask
        if (j0 + 63 > i0 + wid * 16) {
#pragma unroll
            for (int i = 0; i < 2; ++i) {
                const int qi = i0 + wid * 16 + (lane >> 2) + 8 * i;
#pragma unroll
                for (int nt = 0; nt < 8; ++nt) {
                    const int kt0 = j0 + nt * 8 + (lane & 3) * 2;
                    if (kt0 > qi)     sacc[nt][2 * i]     = -1e30f;
                    if (kt0 + 1 > qi) sacc[nt][2 * i + 1] = -1e30f;
                }
            }
        }

        // online softmax (exp2 domain)
#pragma unroll
        for (int i = 0; i < 2; ++i) {
            float mx = -1e30f;
#pragma unroll
            for (int nt = 0; nt < 8; ++nt)
                mx = fmaxf(mx, fmaxf(sacc[nt][2 * i], sacc[nt][2 * i + 1]));
            mx = fmaxf(mx, __shfl_xor_sync(0xffffffffu, mx, 1));
            mx = fmaxf(mx, __shfl_xor_sync(0xffffffffu, mx, 2));
            const float mn = fmaxf(mrow[i], mx);
            const float al = fast_exp2(mrow[i] - mn);
            mrow[i] = mn;
            float sum = 0.f;
#pragma unroll
            for (int nt = 0; nt < 8; ++nt) {
                float p0 = fast_exp2(sacc[nt][2 * i] - mn);
                float p1 = fast_exp2(sacc[nt][2 * i + 1] - mn);
                sacc[nt][2 * i] = p0;
                sacc[nt][2 * i + 1] = p1;
                sum += p0 + p1;
            }
            sum += __shfl_xor_sync(0xffffffffu, sum, 1);
            sum += __shfl_xor_sync(0xffffffffu, sum, 2);
            lrow[i] = lrow[i] * al + sum;
#pragma unroll
            for (int nt = 0; nt < 8; ++nt) {
                oacc[nt][2 * i] *= al;
                oacc[nt][2 * i + 1] *= al;
            }
        }

        // O += P @ V
#pragma unroll
        for (int kt = 0; kt < 4; ++kt) {
            uint32_t pa[4];
            pa[0] = h2pack(sacc[2 * kt][0],     sacc[2 * kt][1]);
            pa[1] = h2pack(sacc[2 * kt][2],     sacc[2 * kt][3]);
            pa[2] = h2pack(sacc[2 * kt + 1][0], sacc[2 * kt + 1][1]);
            pa[3] = h2pack(sacc[2 * kt + 1][2], sacc[2 * kt + 1][3]);
#pragma unroll
            for (int vd = 0; vd < 4; ++vd) {
                uint32_t vh4[4];
                ldsm4t(vh4, sb + AT_ARR + (kt * 16 + vrow) * ROW_B + vcol + vd * 32);
                mma_f16(oacc[2 * vd],     pa, vh4[0], vh4[1]);
                mma_f16(oacc[2 * vd + 1], pa, vh4[2], vh4[3]);
            }
        }
    }

    // epilogue: normalize, write fp16 [b*T+t][h*64+dh]
    const int b = bh >> 4, h = bh & 15;
#pragma unroll
    for (int i = 0; i < 2; ++i) {
        const float inv = 1.0f / lrow[i];
        const int trow = i0 + wid * 16 + (lane >> 2) + 8 * i;
        const size_t rbase = (size_t)(b * TT + trow) * DD + h * 64;
#pragma unroll
        for (int nt = 0; nt < 8; ++nt) {
            const int col = nt * 8 + (lane & 3) * 2;
            *(uint32_t*)(g_attn + rbase + col) =
                h2pack(oacc[nt][2 * i] * inv, oacc[nt][2 * i + 1] * inv);
        }
    }
}

// ---------------------------------------------------------------------------
extern "C" void kernel_launch(void* const* d_in, const int* in_sizes, int n_in,
                              void* d_out, int out_size)
{
    const float* x     = (const float*)d_in[0];
    const float* w_qkv = (const float*)d_in[1];
    const float* b_qkv = (const float*)d_in[2];
    const float* w_out = (const float*)d_in[3];
    const float* b_out = (const float*)d_in[4];
    float* out = (float*)d_out;

    cudaFuncSetAttribute(gemm_mma_kernel,
                         cudaFuncAttributeMaxDynamicSharedMemorySize, GEMM_SMEM);
    cudaFuncSetAttribute(flash_attn_tc_kernel,
                         cudaFuncAttributeMaxDynamicSharedMemorySize, AT_SMEM);

    __half *xh, *wq, *wo, *ah;
    cudaGetSymbolAddress((void**)&xh, g_x);
    cudaGetSymbolAddress((void**)&wq, g_wq);
    cudaGetSymbolAddress((void**)&wo, g_wo);
    cudaGetSymbolAddress((void**)&ah, g_attn);

    // 1. Fused prep: cast x + transpose both weight matrices (one launch)
    prep_kernel<<<PREP_BLKS, 256>>>(x, w_qkv, w_out);
    // 2. QKV projection -> q/k/v fp16 (q pre-scaled into log2 domain)
    gemm_mma_kernel<<<dim3(QKV_N / 128, MROWS / 128), 256, GEMM_SMEM>>>(
        xh, wq, b_qkv, nullptr, QKV_N, 1);
    // 3. Flash attention -> attn fp16
    flash_attn_tc_kernel<<<dim3(TT / 128, BB * HH), 256, AT_SMEM>>>();
    // 4. Output projection (fp32 out)
    gemm_mma_kernel<<<dim3(DD / 128, MROWS / 128), 256, GEMM_SMEM>>>(
        ah, wo, b_out, out, DD, 0);
}